// round 10
// baseline (speedup 1.0000x reference)
#include <cuda_runtime.h>
#include <math.h>

// ---------------- problem constants ----------------
#define BB 128
#define TT 8
#define LL 8
#define HID 64

#define FC1_K 42240
#define FC1_N 256

// ---------------- scratch ----------------
__device__ float g_c1[(size_t)BB * 32 * 94 * 126];
__device__ float g_c2[(size_t)BB * 64 * 46 * 62];
__device__ float g_c3[(size_t)BB * 64 * 22 * 30];
__device__ float g_fc1[BB * FC1_N];
__device__ float g_cnn1[BB * 128];
__device__ float g_cnn2[BB * 128];
__device__ float g_act1[BB * TT * 16];
__device__ float g_a[BB * TT * 16];
__device__ float g_h[LL * TT * BB * HID];
__device__ float g_cst[LL * TT * BB * HID];
__device__ float g_lstm_out[BB * TT * HID];
__device__ float g_out1[BB * TT * 32];
__device__ float g_mo[BB * TT * 4];

// ---------------- tf32 helpers ----------------
__device__ __forceinline__ float tf32r(float x) {
    unsigned u;
    asm("cvt.rna.tf32.f32 %0, %1;" : "=r"(u) : "f"(x));
    return __uint_as_float(u);
}
__device__ __forceinline__ unsigned fu(float x) { return __float_as_uint(x); }

__device__ __forceinline__ void mma_tf32(float* d,
                                         unsigned a0, unsigned a1, unsigned a2, unsigned a3,
                                         unsigned b0, unsigned b1)
{
    asm("mma.sync.aligned.m16n8k8.row.col.f32.tf32.tf32.f32 "
        "{%0,%1,%2,%3}, {%4,%5,%6,%7}, {%8,%9}, {%0,%1,%2,%3};"
        : "+f"(d[0]), "+f"(d[1]), "+f"(d[2]), "+f"(d[3])
        : "r"(a0), "r"(a1), "r"(a2), "r"(a3), "r"(b0), "r"(b1));
}

// ---------------- conv as implicit GEMM on tensor cores (3xTF32 = fp32-accurate) ----
// Block = 128 threads (4 warps). Tile: all CO x (4 ho x 8 wo) spatial.
// mma m16n8k8: A = weights (M=co rows, K), B = im2col patch (K x N), row.col.
// grid: x = spatial tiles (HT*WT), y = batch n.
template <int CIN, int KS, int HI, int WI, int HO, int WO, int CO,
          int CIP, bool RELU>
__global__ void conv_mma(const float* __restrict__ in,
                         const float* __restrict__ wt,
                         const float* __restrict__ bs,
                         float* __restrict__ out)
{
    constexpr int KSQ  = KS * KS;
    constexpr int NTAP = CIN * KSQ;
    constexpr int PR   = 2 * 4 + KS - 2;        // patch rows per ci
    constexpr int PCR  = 2 * 8 + KS - 2;        // real patch cols
    constexpr int PC   = PCR + 1;               // padded
    constexpr int PATCH = CIP * PR * PC;
    constexpr int NPH  = CIN / CIP;             // staging phases
    constexpr int KLOC = CIP * KSQ;             // k per phase (unpadded)
    constexpr int KCH  = (KLOC + 7) / 8;        // k-chunks per phase
    constexpr bool KPADDED = (KLOC % 8) != 0;
    constexpr int WT   = (WO + 7) / 8;
    constexpr int WM   = CO / 16;               // warps along M (2 or 4)
    constexpr int NT_PER = (WM == 4) ? 4 : 2;   // n-subtiles per warp

    __shared__ float Phi[PATCH];
    __shared__ float Plo[PATCH];

    const int tid = threadIdx.x;
    const int w   = tid >> 5;
    const int lane = tid & 31;
    const int g   = lane >> 2;      // groupID 0..7
    const int tig = lane & 3;       // thread in group 0..3
    const int warpM = w % WM;
    const int warpN = w / WM;

    const int tile = blockIdx.x;
    const int n    = blockIdx.y;
    const int ho0  = (tile / WT) * 4;
    const int wo0  = (tile % WT) * 8;
    const int r0   = ho0 * 2;
    const int c0   = wo0 * 2;

    float acc[NT_PER][4];
    #pragma unroll
    for (int t = 0; t < NT_PER; t++)
        #pragma unroll
        for (int i = 0; i < 4; i++) acc[t][i] = 0.0f;

    const int mrow = warpM * 16 + g;

    #pragma unroll 1
    for (int p = 0; p < NPH; p++) {
        if (p) __syncthreads();
        // ---- stage patch (hi/lo tf32 split) ----
        #pragma unroll 1
        for (int idx = tid; idx < PATCH; idx += 128) {
            int ci  = idx / (PR * PC);
            int rem = idx - ci * (PR * PC);
            int r   = rem / PC;
            int c   = rem - r * PC;
            float x = 0.0f;
            int gr = r0 + r, gc = c0 + c;
            if (c < PCR && gr < HI && gc < WI)
                x = in[(((long)n * CIN + p * CIP + ci) * HI + gr) * WI + gc];
            float hi = tf32r(x);
            Phi[idx] = hi;
            Plo[idx] = tf32r(x - hi);
        }
        __syncthreads();

        // ---- K chunks ----
        #pragma unroll 1
        for (int kc = 0; kc < KCH; kc++) {
            int k1 = kc * 8 + tig;      // local k of b0 / a0,a1
            int k2 = k1 + 4;            // local k of b1 / a2,a3
            bool v1 = !KPADDED || (k1 < KLOC);
            bool v2 = !KPADDED || (k2 < KLOC);

            int ci1 = k1 / KSQ, r1 = k1 - ci1 * KSQ;
            int kh1 = r1 / KS,  kw1 = r1 - kh1 * KS;
            int ci2 = k2 / KSQ, r2 = k2 - ci2 * KSQ;
            int kh2 = r2 / KS,  kw2 = r2 - kh2 * KS;
            int off1 = v1 ? (ci1 * (PR * PC) + kh1 * PC + kw1) : 0;
            int off2 = v2 ? (ci2 * (PR * PC) + kh2 * PC + kw2) : 0;

            int kg1 = p * KLOC + k1;
            int kg2 = p * KLOC + k2;

            // A fragment: rows mrow / mrow+8, cols k1 / k2 (weights, L1-hot)
            float w0f = v1 ? __ldg(&wt[(long)mrow * NTAP + kg1])       : 0.0f;
            float w1f = v1 ? __ldg(&wt[(long)(mrow + 8) * NTAP + kg1]) : 0.0f;
            float w2f = v2 ? __ldg(&wt[(long)mrow * NTAP + kg2])       : 0.0f;
            float w3f = v2 ? __ldg(&wt[(long)(mrow + 8) * NTAP + kg2]) : 0.0f;
            float h0 = tf32r(w0f), l0 = tf32r(w0f - h0);
            float h1 = tf32r(w1f), l1 = tf32r(w1f - h1);
            float h2 = tf32r(w2f), l2 = tf32r(w2f - h2);
            float h3 = tf32r(w3f), l3 = tf32r(w3f - h3);

            #pragma unroll
            for (int t = 0; t < NT_PER; t++) {
                int nt = warpN * NT_PER + t;
                int boff = (2 * nt) * PC + 2 * g;
                unsigned b0h = fu(Phi[off1 + boff]);
                unsigned b1h = fu(Phi[off2 + boff]);
                unsigned b0l = fu(Plo[off1 + boff]);
                unsigned b1l = fu(Plo[off2 + boff]);
                // 3xTF32: hi*hi + hi*lo + lo*hi (lo*lo ~ 2^-22, dropped)
                mma_tf32(acc[t], fu(h0), fu(h1), fu(h2), fu(h3), b0h, b1h);
                mma_tf32(acc[t], fu(h0), fu(h1), fu(h2), fu(h3), b0l, b1l);
                mma_tf32(acc[t], fu(l0), fu(l1), fu(l2), fu(l3), b0h, b1h);
            }
        }
    }

    // ---- epilogue: bias (+relu) + store ----
    float bLo = __ldg(&bs[mrow]);
    float bHi = __ldg(&bs[mrow + 8]);
    #pragma unroll
    for (int t = 0; t < NT_PER; t++) {
        int nt = warpN * NT_PER + t;
        int ho = ho0 + nt;
        if (ho >= HO) continue;
        int wo1 = wo0 + 2 * tig;
        int wo2 = wo1 + 1;
        float d0 = acc[t][0] + bLo;
        float d1 = acc[t][1] + bLo;
        float d2 = acc[t][2] + bHi;
        float d3 = acc[t][3] + bHi;
        if (RELU) {
            d0 = fmaxf(d0, 0.0f); d1 = fmaxf(d1, 0.0f);
            d2 = fmaxf(d2, 0.0f); d3 = fmaxf(d3, 0.0f);
        }
        float* o0 = &out[(((long)n * CO + mrow) * HO + ho) * WO];
        float* o8 = &out[(((long)n * CO + mrow + 8) * HO + ho) * WO];
        if (wo1 < WO) { o0[wo1] = d0; o8[wo1] = d2; }
        if (wo2 < WO) { o0[wo2] = d1; o8[wo2] = d3; }
    }
}

// ---------------- fc1 ----------------
__global__ void fc1_init_kernel(const float* __restrict__ b, float* __restrict__ C)
{
    int idx = blockIdx.x * blockDim.x + threadIdx.x;
    if (idx < BB * FC1_N) C[idx] = b[idx % FC1_N];
}

__global__ void fc1_gemm_kernel(const float* __restrict__ A,
                                const float* __restrict__ B,
                                float* __restrict__ C)
{
    __shared__ __align__(16) float As[16][72];
    __shared__ __align__(16) float Bs[16][72];

    const int tid = threadIdx.x;
    const int m0 = blockIdx.y * 64;
    const int n0 = blockIdx.x * 64;
    const int k0 = blockIdx.z * 1280;

    const int lr = tid >> 2;
    const int lc = (tid & 3) * 4;

    const float* Ap = A + (long)(m0 + lr) * FC1_K + k0 + lc;
    const float* Bp = B + (long)(n0 + lr) * FC1_K + k0 + lc;

    const int ty = tid >> 4, tx = tid & 15;
    float acc[4][4] = {};

    for (int it = 0; it < 80; it++) {
        float4 av = *reinterpret_cast<const float4*>(Ap + it * 16);
        float4 bv = *reinterpret_cast<const float4*>(Bp + it * 16);
        __syncthreads();
        As[lc + 0][lr] = av.x; As[lc + 1][lr] = av.y; As[lc + 2][lr] = av.z; As[lc + 3][lr] = av.w;
        Bs[lc + 0][lr] = bv.x; Bs[lc + 1][lr] = bv.y; Bs[lc + 2][lr] = bv.z; Bs[lc + 3][lr] = bv.w;
        __syncthreads();
        #pragma unroll
        for (int kk = 0; kk < 16; kk++) {
            float4 a4 = *reinterpret_cast<const float4*>(&As[kk][ty * 4]);
            float4 b4 = *reinterpret_cast<const float4*>(&Bs[kk][tx * 4]);
            float a[4] = {a4.x, a4.y, a4.z, a4.w};
            float b[4] = {b4.x, b4.y, b4.z, b4.w};
            #pragma unroll
            for (int i = 0; i < 4; i++)
                #pragma unroll
                for (int j = 0; j < 4; j++)
                    acc[i][j] += a[i] * b[j];
        }
    }

    #pragma unroll
    for (int i = 0; i < 4; i++)
        #pragma unroll
        for (int j = 0; j < 4; j++)
            atomicAdd(&C[(m0 + ty * 4 + i) * FC1_N + (n0 + tx * 4 + j)], acc[i][j]);
}

// ---------------- small linear ----------------
__global__ void lin2_kernel(const float* __restrict__ in,
                            const float* __restrict__ w,
                            const float* __restrict__ bias,
                            float* __restrict__ out,
                            int M, int N, int K, int reluIn)
{
    __shared__ float Xs[256 * 33];

    const int tid = threadIdx.x;
    const int m0 = blockIdx.x * 32;
    const int n0 = blockIdx.y * 32;

    for (int idx = tid; idx < 32 * K; idx += 256) {
        int m_l = idx / K;
        int k = idx - m_l * K;
        float v = in[(long)(m0 + m_l) * K + k];
        if (reluIn) v = fmaxf(v, 0.0f);
        Xs[k * 33 + m_l] = v;
    }
    __syncthreads();

    const int lane = tid & 31;
    const int wg = tid >> 5;
    const int m = m0 + lane;

    float acc[4] = {0.f, 0.f, 0.f, 0.f};
    const int K4 = K & ~3;

    for (int k4 = 0; k4 < K4; k4 += 4) {
        float xv0 = Xs[(k4 + 0) * 33 + lane];
        float xv1 = Xs[(k4 + 1) * 33 + lane];
        float xv2 = Xs[(k4 + 2) * 33 + lane];
        float xv3 = Xs[(k4 + 3) * 33 + lane];
        #pragma unroll
        for (int ni = 0; ni < 4; ni++) {
            int nn = n0 + wg * 4 + ni;
            if (nn < N) {
                float4 wv = *reinterpret_cast<const float4*>(&w[(long)nn * K + k4]);
                acc[ni] += xv0 * wv.x + xv1 * wv.y + xv2 * wv.z + xv3 * wv.w;
            }
        }
    }
    for (int k = K4; k < K; k++) {
        float xv = Xs[k * 33 + lane];
        #pragma unroll
        for (int ni = 0; ni < 4; ni++) {
            int nn = n0 + wg * 4 + ni;
            if (nn < N) acc[ni] += xv * w[(long)nn * K + k];
        }
    }

    #pragma unroll
    for (int ni = 0; ni < 4; ni++) {
        int nn = n0 + wg * 4 + ni;
        if (nn < N) out[(long)m * N + nn] = acc[ni] + bias[nn];
    }
}

// ---------------- LSTM wave kernel (15 launches — measured faster than fused) ----
__device__ __forceinline__ float sigf(float x) { return 1.0f / (1.0f + expf(-x)); }

__global__ void lstm_wave2_kernel(int wave,
                                  const float* __restrict__ a,
                                  const float* __restrict__ cnn2,
                                  const float* __restrict__ Wih0,
                                  const float* __restrict__ Wih,
                                  const float* __restrict__ Whh,
                                  const float* __restrict__ bih,
                                  const float* __restrict__ bhh,
                                  float* __restrict__ h_arr,
                                  float* __restrict__ c_arr,
                                  float* __restrict__ lstm_out)
{
    __shared__ float Ws[32 * 257];
    __shared__ float Xs[32 * 9];

    const int cell = blockIdx.x >> 4;
    const int bblk = blockIdx.x & 15;
    int l_lo = wave - (TT - 1); if (l_lo < 0) l_lo = 0;
    const int l = l_lo + cell;
    const int t = wave - l;

    const int tid = threadIdx.x;
    const int j = tid & 63;
    const int bq = tid >> 6;
    const int b0 = bblk * 8;

    float acc[4][2];
    #pragma unroll
    for (int q = 0; q < 4; q++) {
        float bb = bih[l * 256 + q * 64 + j] + bhh[l * 256 + q * 64 + j];
        acc[q][0] = bb; acc[q][1] = bb;
    }

    #pragma unroll 1
    for (int ph = 0; ph < 2; ph++) {
        const float* W;
        const float* xbase;
        int K, xstr;
        if (ph == 0) {
            if (l == 0) { W = Wih0; K = 16; xbase = a + t * 16; xstr = TT * 16; }
            else        { W = Wih + (long)(l - 1) * 256 * 64; K = 64;
                          xbase = h_arr + ((long)((l - 1) * TT + t)) * BB * 64; xstr = 64; }
        } else {
            W = Whh + (long)l * 256 * 64; K = 64;
            if (t == 0) { xbase = cnn2 + HID; xstr = 128; }
            else        { xbase = h_arr + ((long)(l * TT + (t - 1))) * BB * 64; xstr = 64; }
        }

        for (int k0 = 0; k0 < K; k0 += 32) {
            int kc = (K - k0 < 32) ? (K - k0) : 32;
            __syncthreads();
            for (int idx = tid; idx < kc * 256; idx += 256) {
                int r = idx / kc;
                int k = idx - r * kc;
                Ws[k * 257 + r] = W[(long)r * K + k0 + k];
            }
            for (int idx = tid; idx < kc * 8; idx += 256) {
                int b_l = idx / kc;
                int k = idx - b_l * kc;
                Xs[k * 9 + b_l] = xbase[(long)(b0 + b_l) * xstr + k0 + k];
            }
            __syncthreads();
            #pragma unroll 8
            for (int k = 0; k < kc; k++) {
                float xv0 = Xs[k * 9 + (bq << 1)];
                float xv1 = Xs[k * 9 + (bq << 1) + 1];
                float w0 = Ws[k * 257 + j];
                float w1 = Ws[k * 257 + 64 + j];
                float w2 = Ws[k * 257 + 128 + j];
                float w3 = Ws[k * 257 + 192 + j];
                acc[0][0] += w0 * xv0; acc[0][1] += w0 * xv1;
                acc[1][0] += w1 * xv0; acc[1][1] += w1 * xv1;
                acc[2][0] += w2 * xv0; acc[2][1] += w2 * xv1;
                acc[3][0] += w3 * xv0; acc[3][1] += w3 * xv1;
            }
        }
    }

    #pragma unroll
    for (int i = 0; i < 2; i++) {
        int b = b0 + (bq << 1) + i;
        float c_prev = (t == 0) ? cnn2[b * 128 + j]
                                : c_arr[((long)(l * TT + (t - 1)) * BB + b) * 64 + j];
        float i_ = sigf(acc[0][i]);
        float f_ = sigf(acc[1][i]);
        float gg = tanhf(acc[2][i]);
        float o_ = sigf(acc[3][i]);
        float c  = f_ * c_prev + i_ * gg;
        float h  = o_ * tanhf(c);
        long pos = ((long)(l * TT + t) * BB + b) * 64 + j;
        h_arr[pos] = h;
        c_arr[pos] = c;
        if (l == LL - 1) lstm_out[(b * TT + t) * 64 + j] = h;
    }
}

// ---------------- finalize ----------------
__global__ void finalize_kernel(const float* __restrict__ mo,
                                const float* __restrict__ gt,
                                float* __restrict__ out)
{
    int idx = blockIdx.x * blockDim.x + threadIdx.x;
    if (idx >= BB * TT) return;
    int b = idx / TT;
    float yaw = gt[b * (TT * 6) + 5];
    float cy = cosf(yaw), sy = sinf(yaw);
    float m0 = mo[idx * 4 + 0];
    float m1 = mo[idx * 4 + 1];
    float m2 = mo[idx * 4 + 2];
    float m3 = mo[idx * 4 + 3];
    float tx = gt[b * (TT * 6) + 1];
    float ty = gt[b * (TT * 6) + 2];
    float tz = gt[b * (TT * 6) + 3];
    out[idx * 4 + 0] =  m0 * cy + m1 * sy + tx;
    out[idx * 4 + 1] = -m0 * sy + m1 * cy + ty;
    out[idx * 4 + 2] =  m2 + tz;
    out[idx * 4 + 3] =  m3;
}

// ---------------- launch ----------------
extern "C" void kernel_launch(void* const* d_in, const int* in_sizes, int n_in,
                              void* d_out, int out_size)
{
    const float* image    = (const float*)d_in[0];
    const float* act_in   = (const float*)d_in[1];
    const float* gt       = (const float*)d_in[2];
    const float* conv1_w  = (const float*)d_in[3];
    const float* conv1_b  = (const float*)d_in[4];
    const float* conv2_w  = (const float*)d_in[5];
    const float* conv2_b  = (const float*)d_in[6];
    const float* conv3_w  = (const float*)d_in[7];
    const float* conv3_b  = (const float*)d_in[8];
    const float* fc1_w    = (const float*)d_in[9];
    const float* fc1_b    = (const float*)d_in[10];
    const float* fc2_w    = (const float*)d_in[11];
    const float* fc2_b    = (const float*)d_in[12];
    const float* lowd1_w  = (const float*)d_in[13];
    const float* lowd1_b  = (const float*)d_in[14];
    const float* lowd2_w  = (const float*)d_in[15];
    const float* lowd2_b  = (const float*)d_in[16];
    const float* act1_w   = (const float*)d_in[17];
    const float* act1_b   = (const float*)d_in[18];
    const float* act2_w   = (const float*)d_in[19];
    const float* act2_b   = (const float*)d_in[20];
    const float* Wih0     = (const float*)d_in[21];
    const float* Wih      = (const float*)d_in[22];
    const float* Whh      = (const float*)d_in[23];
    const float* bih      = (const float*)d_in[24];
    const float* bhh      = (const float*)d_in[25];
    const float* out1_w   = (const float*)d_in[26];
    const float* out1_b   = (const float*)d_in[27];
    const float* out2_w   = (const float*)d_in[28];
    const float* out2_b   = (const float*)d_in[29];
    float* out = (float*)d_out;

    float *c1, *c2, *c3, *fc1o, *cnn1, *cnn2, *a1, *a2, *hA, *cA, *lo, *o1, *mo;
    cudaGetSymbolAddress((void**)&c1,   g_c1);
    cudaGetSymbolAddress((void**)&c2,   g_c2);
    cudaGetSymbolAddress((void**)&c3,   g_c3);
    cudaGetSymbolAddress((void**)&fc1o, g_fc1);
    cudaGetSymbolAddress((void**)&cnn1, g_cnn1);
    cudaGetSymbolAddress((void**)&cnn2, g_cnn2);
    cudaGetSymbolAddress((void**)&a1,   g_act1);
    cudaGetSymbolAddress((void**)&a2,   g_a);
    cudaGetSymbolAddress((void**)&hA,   g_h);
    cudaGetSymbolAddress((void**)&cA,   g_cst);
    cudaGetSymbolAddress((void**)&lo,   g_lstm_out);
    cudaGetSymbolAddress((void**)&o1,   g_out1);
    cudaGetSymbolAddress((void**)&mo,   g_mo);

    // #1 conv1 (relu): tiles = ceil(94/4)=24 x ceil(126/8)=16 = 384
    conv_mma<3, 5, 192, 256, 94, 126, 32, 3, true>
        <<<dim3(384, BB), 128>>>(image, conv1_w, conv1_b, c1);
    // #2, #3: action path (independent)
    { dim3 g(BB * TT / 32, 1); lin2_kernel<<<g, 256>>>(act_in, act1_w, act1_b, a1, BB * TT, 16, 2, 0); }
    { dim3 g(BB * TT / 32, 1); lin2_kernel<<<g, 256>>>(a1, act2_w, act2_b, a2, BB * TT, 16, 16, 1); }
    // #4 conv2 (relu): tiles = 12 x 8 = 96
    conv_mma<32, 3, 94, 126, 46, 62, 64, 32, true>
        <<<dim3(96, BB), 128>>>(c1, conv2_w, conv2_b, c2);
    // #5 fc1 bias init (independent)
    fc1_init_kernel<<<(BB * FC1_N + 255) / 256, 256>>>(fc1_b, fc1o);
    // #6 conv3 (no relu): tiles = 6 x 4 = 24, 2 staging phases (32 ci each)
    conv_mma<64, 3, 46, 62, 22, 30, 64, 32, false>
        <<<dim3(24, BB), 128>>>(c2, conv3_w, conv3_b, c3);
    // #7 fc1 split-K GEMM
    {
        dim3 grid(FC1_N / 64, BB / 64, 33);
        fc1_gemm_kernel<<<grid, 256>>>(c3, fc1_w, fc1o);
    }
    // fc2 / lowd chain
    { dim3 g(BB / 32, 4); lin2_kernel<<<g, 256>>>(fc1o, fc2_w, fc2_b, cnn1, BB, 128, 256, 1); }
    { dim3 g(BB / 32, 4); lin2_kernel<<<g, 256>>>(cnn1, lowd1_w, lowd1_b, cnn2, BB, 128, 128, 0); }
    { dim3 g(BB / 32, 4); lin2_kernel<<<g, 256>>>(cnn2, lowd2_w, lowd2_b, cnn1, BB, 128, 128, 1); }

    // LSTM: 15 waves
    for (int w = 0; w < LL + TT - 1; w++) {
        int l_lo = w - (TT - 1); if (l_lo < 0) l_lo = 0;
        int l_hi = w; if (l_hi > LL - 1) l_hi = LL - 1;
        int ncells = l_hi - l_lo + 1;
        lstm_wave2_kernel<<<ncells * 16, 256>>>(w, a2, cnn1, Wih0, Wih, Whh, bih, bhh, hA, cA, lo);
    }

    // heads
    { dim3 g(BB * TT / 32, 1); lin2_kernel<<<g, 256>>>(lo, out1_w, out1_b, o1, BB * TT, 32, 64, 0); }
    { dim3 g(BB * TT / 32, 1); lin2_kernel<<<g, 256>>>(o1, out2_w, out2_b, mo, BB * TT, 4, 32, 1); }

    finalize_kernel<<<(BB * TT + 255) / 256, 256>>>(mo, gt, out);
}

// round 12
// speedup vs baseline: 1.0791x; 1.0791x over previous
#include <cuda_runtime.h>
#include <math.h>

// ---------------- problem constants ----------------
#define BB 128
#define TT 8
#define LL 8
#define HID 64

#define FC1_K 42240
#define FC1_N 256

// ---------------- scratch ----------------
__device__ float g_c1[(size_t)BB * 32 * 94 * 126];
__device__ float g_c2[(size_t)BB * 64 * 46 * 62];
__device__ float g_c3[(size_t)BB * 64 * 22 * 30];
__device__ float g_fc1[BB * FC1_N];
__device__ float g_cnn1[BB * 128];
__device__ float g_cnn2[BB * 128];
__device__ float g_act1[BB * TT * 16];
__device__ float g_a[BB * TT * 16];
__device__ float g_h[LL * TT * BB * HID];
__device__ float g_cst[LL * TT * BB * HID];
__device__ float g_lstm_out[BB * TT * HID];
__device__ float g_out1[BB * TT * 32];
__device__ float g_mo[BB * TT * 4];

// split-weight scratch (hi/lo tf32 pairs, k padded to mult of 8 per phase)
__device__ float2 g_w1s[32 * 80];     // conv1: CO=32, KTOT=80 (75 padded, pad weights = 0)
__device__ float2 g_w2s[64 * 288];    // conv2: CO=64, KTOT=288 (2 phases x 144)
__device__ float2 g_w3s[64 * 576];    // conv3: CO=64, KTOT=576 (4 phases x 144)

// ---------------- tf32 helpers ----------------
__device__ __forceinline__ float tf32r(float x) {
    unsigned u;
    asm("cvt.rna.tf32.f32 %0, %1;" : "=r"(u) : "f"(x));
    return __uint_as_float(u);
}
__device__ __forceinline__ unsigned fu(float x) { return __float_as_uint(x); }

__device__ __forceinline__ void mma_tf32(float* d,
                                         unsigned a0, unsigned a1, unsigned a2, unsigned a3,
                                         unsigned b0, unsigned b1)
{
    asm("mma.sync.aligned.m16n8k8.row.col.f32.tf32.tf32.f32 "
        "{%0,%1,%2,%3}, {%4,%5,%6,%7}, {%8,%9}, {%0,%1,%2,%3};"
        : "+f"(d[0]), "+f"(d[1]), "+f"(d[2]), "+f"(d[3])
        : "r"(a0), "r"(a1), "r"(a2), "r"(a3), "r"(b0), "r"(b1));
}

// ---------------- weight split prep ----------------
__global__ void wsplit_kernel(const float* __restrict__ src, float2* __restrict__ dst,
                              int CO, int NPH, int KLOC, int KLOCP)
{
    int KT = NPH * KLOCP;
    int idx = blockIdx.x * blockDim.x + threadIdx.x;
    if (idx >= CO * KT) return;
    int co = idx / KT, kg = idx - co * KT;
    int p = kg / KLOCP, kp = kg - p * KLOCP;
    float v = (kp < KLOC) ? src[(long)co * (NPH * KLOC) + p * KLOC + kp] : 0.0f;
    float hi = tf32r(v);
    dst[idx] = make_float2(hi, tf32r(v - hi));
}

// ---------------- conv as implicit GEMM on tensor cores (3xTF32) v2 ------------
// Block = 128 threads (4 warps). Tile: all CO x (4 ho x 8 wo).
// LUT-based patch offsets, float2(hi,lo) packed patch + weights.
// Padded k entries: LUT = 0 (ANY valid offset) — their weights are zero, so the
// mma contribution is exactly zero regardless of B value. (R11 bug: LUT=PATCH
// sentinel + boff overran the P array -> illegal memory access.)
template <int CIN, int KS, int HI, int WI, int HO, int WO, int CO,
          int CIP, bool RELU>
__global__ void conv_mma2(const float* __restrict__ in,
                          const float2* __restrict__ wsp,
                          const float* __restrict__ bs,
                          float* __restrict__ out)
{
    constexpr int KSQ   = KS * KS;
    constexpr int PR    = 2 * 4 + KS - 2;
    constexpr int PCR   = 2 * 8 + KS - 2;
    constexpr int PC    = PCR + 1;
    constexpr int PATCH = CIP * PR * PC;
    constexpr int NPH   = CIN / CIP;
    constexpr int KLOC  = CIP * KSQ;
    constexpr int KLOCP = ((KLOC + 7) / 8) * 8;
    constexpr int KCH   = KLOCP / 8;
    constexpr int KTOT  = NPH * KLOCP;
    constexpr int WT    = (WO + 7) / 8;
    constexpr int WM    = CO / 16;
    constexpr int NT_PER = (WM == 4) ? 4 : 2;

    __shared__ __align__(8) float2 P[PATCH];
    __shared__ int LUT[KLOCP];

    const int tid  = threadIdx.x;
    const int w    = tid >> 5;
    const int lane = tid & 31;
    const int g    = lane >> 2;
    const int tig  = lane & 3;
    const int warpM = w % WM;
    const int warpN = w / WM;

    const int tile = blockIdx.x;
    const int n    = blockIdx.y;
    const int ho0  = (tile / WT) * 4;
    const int wo0  = (tile % WT) * 8;
    const int r0   = ho0 * 2;
    const int c0   = wo0 * 2;

    // LUT (once); padded entries -> 0 (weights there are zero)
    for (int k = tid; k < KLOCP; k += 128) {
        if (k < KLOC) {
            int ci = k / KSQ, r = k - ci * KSQ;
            int kh = r / KS,  kw = r - kh * KS;
            LUT[k] = ci * (PR * PC) + kh * PC + kw;
        } else {
            LUT[k] = 0;
        }
    }

    float acc[NT_PER][4];
    #pragma unroll
    for (int t = 0; t < NT_PER; t++)
        #pragma unroll
        for (int i = 0; i < 4; i++) acc[t][i] = 0.0f;

    const int mrow = warpM * 16 + g;
    const float2* wr0 = wsp + (long)mrow * KTOT;
    const float2* wr8 = wsp + (long)(mrow + 8) * KTOT;

    #pragma unroll 1
    for (int p = 0; p < NPH; p++) {
        __syncthreads();   // LUT ready (p=0) / previous patch consumed
        // ---- stage patch (hi/lo split, packed) ----
        #pragma unroll 1
        for (int idx = tid; idx < PATCH; idx += 128) {
            int ci  = idx / (PR * PC);
            int rem = idx - ci * (PR * PC);
            int r   = rem / PC;
            int c   = rem - r * PC;
            float x = 0.0f;
            int gr = r0 + r, gc = c0 + c;
            if (c < PCR && gr < HI && gc < WI)
                x = in[(((long)n * CIN + p * CIP + ci) * HI + gr) * WI + gc];
            float hi = tf32r(x);
            P[idx] = make_float2(hi, tf32r(x - hi));
        }
        __syncthreads();

        const int kbase = p * KLOCP;
        #pragma unroll 1
        for (int kc = 0; kc < KCH; kc++) {
            int k1 = kc * 8 + tig;
            int k2 = k1 + 4;
            int off1 = LUT[k1];
            int off2 = LUT[k2];

            float2 wa0 = __ldg(&wr0[kbase + k1]);
            float2 wa1 = __ldg(&wr8[kbase + k1]);
            float2 wa2 = __ldg(&wr0[kbase + k2]);
            float2 wa3 = __ldg(&wr8[kbase + k2]);

            #pragma unroll
            for (int t = 0; t < NT_PER; t++) {
                int nt = warpN * NT_PER + t;
                int boff = (2 * nt) * PC + 2 * g;
                float2 b0 = P[off1 + boff];
                float2 b1 = P[off2 + boff];
                // 3xTF32: hi*hi + hi*lo + lo*hi
                mma_tf32(acc[t], fu(wa0.x), fu(wa1.x), fu(wa2.x), fu(wa3.x), fu(b0.x), fu(b1.x));
                mma_tf32(acc[t], fu(wa0.x), fu(wa1.x), fu(wa2.x), fu(wa3.x), fu(b0.y), fu(b1.y));
                mma_tf32(acc[t], fu(wa0.y), fu(wa1.y), fu(wa2.y), fu(wa3.y), fu(b0.x), fu(b1.x));
            }
        }
    }

    // ---- epilogue ----
    float bLo = __ldg(&bs[mrow]);
    float bHi = __ldg(&bs[mrow + 8]);
    #pragma unroll
    for (int t = 0; t < NT_PER; t++) {
        int nt = warpN * NT_PER + t;
        int ho = ho0 + nt;
        if (ho >= HO) continue;
        int wo1 = wo0 + 2 * tig;
        int wo2 = wo1 + 1;
        float d0 = acc[t][0] + bLo;
        float d1 = acc[t][1] + bLo;
        float d2 = acc[t][2] + bHi;
        float d3 = acc[t][3] + bHi;
        if (RELU) {
            d0 = fmaxf(d0, 0.0f); d1 = fmaxf(d1, 0.0f);
            d2 = fmaxf(d2, 0.0f); d3 = fmaxf(d3, 0.0f);
        }
        float* o0 = &out[(((long)n * CO + mrow) * HO + ho) * WO];
        float* o8 = &out[(((long)n * CO + mrow + 8) * HO + ho) * WO];
        if (wo1 < WO) { o0[wo1] = d0; o8[wo1] = d2; }
        if (wo2 < WO) { o0[wo2] = d1; o8[wo2] = d3; }
    }
}

// ---------------- fc1 ----------------
__global__ void fc1_init_kernel(const float* __restrict__ b, float* __restrict__ C)
{
    int idx = blockIdx.x * blockDim.x + threadIdx.x;
    if (idx < BB * FC1_N) C[idx] = b[idx % FC1_N];
}

__global__ void fc1_gemm_kernel(const float* __restrict__ A,
                                const float* __restrict__ B,
                                float* __restrict__ C)
{
    __shared__ __align__(16) float As[16][72];
    __shared__ __align__(16) float Bs[16][72];

    const int tid = threadIdx.x;
    const int m0 = blockIdx.y * 64;
    const int n0 = blockIdx.x * 64;
    const int k0 = blockIdx.z * 1280;

    const int lr = tid >> 2;
    const int lc = (tid & 3) * 4;

    const float* Ap = A + (long)(m0 + lr) * FC1_K + k0 + lc;
    const float* Bp = B + (long)(n0 + lr) * FC1_K + k0 + lc;

    const int ty = tid >> 4, tx = tid & 15;
    float acc[4][4] = {};

    for (int it = 0; it < 80; it++) {
        float4 av = *reinterpret_cast<const float4*>(Ap + it * 16);
        float4 bv = *reinterpret_cast<const float4*>(Bp + it * 16);
        __syncthreads();
        As[lc + 0][lr] = av.x; As[lc + 1][lr] = av.y; As[lc + 2][lr] = av.z; As[lc + 3][lr] = av.w;
        Bs[lc + 0][lr] = bv.x; Bs[lc + 1][lr] = bv.y; Bs[lc + 2][lr] = bv.z; Bs[lc + 3][lr] = bv.w;
        __syncthreads();
        #pragma unroll
        for (int kk = 0; kk < 16; kk++) {
            float4 a4 = *reinterpret_cast<const float4*>(&As[kk][ty * 4]);
            float4 b4 = *reinterpret_cast<const float4*>(&Bs[kk][tx * 4]);
            float a[4] = {a4.x, a4.y, a4.z, a4.w};
            float b[4] = {b4.x, b4.y, b4.z, b4.w};
            #pragma unroll
            for (int i = 0; i < 4; i++)
                #pragma unroll
                for (int j = 0; j < 4; j++)
                    acc[i][j] += a[i] * b[j];
        }
    }

    #pragma unroll
    for (int i = 0; i < 4; i++)
        #pragma unroll
        for (int j = 0; j < 4; j++)
            atomicAdd(&C[(m0 + ty * 4 + i) * FC1_N + (n0 + tx * 4 + j)], acc[i][j]);
}

// ---------------- small linear ----------------
__global__ void lin2_kernel(const float* __restrict__ in,
                            const float* __restrict__ w,
                            const float* __restrict__ bias,
                            float* __restrict__ out,
                            int M, int N, int K, int reluIn)
{
    __shared__ float Xs[256 * 33];

    const int tid = threadIdx.x;
    const int m0 = blockIdx.x * 32;
    const int n0 = blockIdx.y * 32;

    for (int idx = tid; idx < 32 * K; idx += 256) {
        int m_l = idx / K;
        int k = idx - m_l * K;
        float v = in[(long)(m0 + m_l) * K + k];
        if (reluIn) v = fmaxf(v, 0.0f);
        Xs[k * 33 + m_l] = v;
    }
    __syncthreads();

    const int lane = tid & 31;
    const int wg = tid >> 5;
    const int m = m0 + lane;

    float acc[4] = {0.f, 0.f, 0.f, 0.f};
    const int K4 = K & ~3;

    for (int k4 = 0; k4 < K4; k4 += 4) {
        float xv0 = Xs[(k4 + 0) * 33 + lane];
        float xv1 = Xs[(k4 + 1) * 33 + lane];
        float xv2 = Xs[(k4 + 2) * 33 + lane];
        float xv3 = Xs[(k4 + 3) * 33 + lane];
        #pragma unroll
        for (int ni = 0; ni < 4; ni++) {
            int nn = n0 + wg * 4 + ni;
            if (nn < N) {
                float4 wv = *reinterpret_cast<const float4*>(&w[(long)nn * K + k4]);
                acc[ni] += xv0 * wv.x + xv1 * wv.y + xv2 * wv.z + xv3 * wv.w;
            }
        }
    }
    for (int k = K4; k < K; k++) {
        float xv = Xs[k * 33 + lane];
        #pragma unroll
        for (int ni = 0; ni < 4; ni++) {
            int nn = n0 + wg * 4 + ni;
            if (nn < N) acc[ni] += xv * w[(long)nn * K + k];
        }
    }

    #pragma unroll
    for (int ni = 0; ni < 4; ni++) {
        int nn = n0 + wg * 4 + ni;
        if (nn < N) out[(long)m * N + nn] = acc[ni] + bias[nn];
    }
}

// ---------------- LSTM wave kernel ----------------
__device__ __forceinline__ float sigf(float x) { return 1.0f / (1.0f + expf(-x)); }

__global__ void lstm_wave2_kernel(int wave,
                                  const float* __restrict__ a,
                                  const float* __restrict__ cnn2,
                                  const float* __restrict__ Wih0,
                                  const float* __restrict__ Wih,
                                  const float* __restrict__ Whh,
                                  const float* __restrict__ bih,
                                  const float* __restrict__ bhh,
                                  float* __restrict__ h_arr,
                                  float* __restrict__ c_arr,
                                  float* __restrict__ lstm_out)
{
    __shared__ float Ws[32 * 257];
    __shared__ float Xs[32 * 9];

    const int cell = blockIdx.x >> 4;
    const int bblk = blockIdx.x & 15;
    int l_lo = wave - (TT - 1); if (l_lo < 0) l_lo = 0;
    const int l = l_lo + cell;
    const int t = wave - l;

    const int tid = threadIdx.x;
    const int j = tid & 63;
    const int bq = tid >> 6;
    const int b0 = bblk * 8;

    float acc[4][2];
    #pragma unroll
    for (int q = 0; q < 4; q++) {
        float bb = bih[l * 256 + q * 64 + j] + bhh[l * 256 + q * 64 + j];
        acc[q][0] = bb; acc[q][1] = bb;
    }

    #pragma unroll 1
    for (int ph = 0; ph < 2; ph++) {
        const float* W;
        const float* xbase;
        int K, xstr;
        if (ph == 0) {
            if (l == 0) { W = Wih0; K = 16; xbase = a + t * 16; xstr = TT * 16; }
            else        { W = Wih + (long)(l - 1) * 256 * 64; K = 64;
                          xbase = h_arr + ((long)((l - 1) * TT + t)) * BB * 64; xstr = 64; }
        } else {
            W = Whh + (long)l * 256 * 64; K = 64;
            if (t == 0) { xbase = cnn2 + HID; xstr = 128; }
            else        { xbase = h_arr + ((long)(l * TT + (t - 1))) * BB * 64; xstr = 64; }
        }

        for (int k0 = 0; k0 < K; k0 += 32) {
            int kc = (K - k0 < 32) ? (K - k0) : 32;
            __syncthreads();
            for (int idx = tid; idx < kc * 256; idx += 256) {
                int r = idx / kc;
                int k = idx - r * kc;
                Ws[k * 257 + r] = W[(long)r * K + k0 + k];
            }
            for (int idx = tid; idx < kc * 8; idx += 256) {
                int b_l = idx / kc;
                int k = idx - b_l * kc;
                Xs[k * 9 + b_l] = xbase[(long)(b0 + b_l) * xstr + k0 + k];
            }
            __syncthreads();
            #pragma unroll 8
            for (int k = 0; k < kc; k++) {
                float xv0 = Xs[k * 9 + (bq << 1)];
                float xv1 = Xs[k * 9 + (bq << 1) + 1];
                float w0 = Ws[k * 257 + j];
                float w1 = Ws[k * 257 + 64 + j];
                float w2 = Ws[k * 257 + 128 + j];
                float w3 = Ws[k * 257 + 192 + j];
                acc[0][0] += w0 * xv0; acc[0][1] += w0 * xv1;
                acc[1][0] += w1 * xv0; acc[1][1] += w1 * xv1;
                acc[2][0] += w2 * xv0; acc[2][1] += w2 * xv1;
                acc[3][0] += w3 * xv0; acc[3][1] += w3 * xv1;
            }
        }
    }

    #pragma unroll
    for (int i = 0; i < 2; i++) {
        int b = b0 + (bq << 1) + i;
        float c_prev = (t == 0) ? cnn2[b * 128 + j]
                                : c_arr[((long)(l * TT + (t - 1)) * BB + b) * 64 + j];
        float i_ = sigf(acc[0][i]);
        float f_ = sigf(acc[1][i]);
        float gg = tanhf(acc[2][i]);
        float o_ = sigf(acc[3][i]);
        float c  = f_ * c_prev + i_ * gg;
        float h  = o_ * tanhf(c);
        long pos = ((long)(l * TT + t) * BB + b) * 64 + j;
        h_arr[pos] = h;
        c_arr[pos] = c;
        if (l == LL - 1) lstm_out[(b * TT + t) * 64 + j] = h;
    }
}

// ---------------- finalize ----------------
__global__ void finalize_kernel(const float* __restrict__ mo,
                                const float* __restrict__ gt,
                                float* __restrict__ out)
{
    int idx = blockIdx.x * blockDim.x + threadIdx.x;
    if (idx >= BB * TT) return;
    int b = idx / TT;
    float yaw = gt[b * (TT * 6) + 5];
    float cy = cosf(yaw), sy = sinf(yaw);
    float m0 = mo[idx * 4 + 0];
    float m1 = mo[idx * 4 + 1];
    float m2 = mo[idx * 4 + 2];
    float m3 = mo[idx * 4 + 3];
    float tx = gt[b * (TT * 6) + 1];
    float ty = gt[b * (TT * 6) + 2];
    float tz = gt[b * (TT * 6) + 3];
    out[idx * 4 + 0] =  m0 * cy + m1 * sy + tx;
    out[idx * 4 + 1] = -m0 * sy + m1 * cy + ty;
    out[idx * 4 + 2] =  m2 + tz;
    out[idx * 4 + 3] =  m3;
}

// ---------------- launch ----------------
extern "C" void kernel_launch(void* const* d_in, const int* in_sizes, int n_in,
                              void* d_out, int out_size)
{
    const float* image    = (const float*)d_in[0];
    const float* act_in   = (const float*)d_in[1];
    const float* gt       = (const float*)d_in[2];
    const float* conv1_w  = (const float*)d_in[3];
    const float* conv1_b  = (const float*)d_in[4];
    const float* conv2_w  = (const float*)d_in[5];
    const float* conv2_b  = (const float*)d_in[6];
    const float* conv3_w  = (const float*)d_in[7];
    const float* conv3_b  = (const float*)d_in[8];
    const float* fc1_w    = (const float*)d_in[9];
    const float* fc1_b    = (const float*)d_in[10];
    const float* fc2_w    = (const float*)d_in[11];
    const float* fc2_b    = (const float*)d_in[12];
    const float* lowd1_w  = (const float*)d_in[13];
    const float* lowd1_b  = (const float*)d_in[14];
    const float* lowd2_w  = (const float*)d_in[15];
    const float* lowd2_b  = (const float*)d_in[16];
    const float* act1_w   = (const float*)d_in[17];
    const float* act1_b   = (const float*)d_in[18];
    const float* act2_w   = (const float*)d_in[19];
    const float* act2_b   = (const float*)d_in[20];
    const float* Wih0     = (const float*)d_in[21];
    const float* Wih      = (const float*)d_in[22];
    const float* Whh      = (const float*)d_in[23];
    const float* bih      = (const float*)d_in[24];
    const float* bhh      = (const float*)d_in[25];
    const float* out1_w   = (const float*)d_in[26];
    const float* out1_b   = (const float*)d_in[27];
    const float* out2_w   = (const float*)d_in[28];
    const float* out2_b   = (const float*)d_in[29];
    float* out = (float*)d_out;

    float *c1, *c2, *c3, *fc1o, *cnn1, *cnn2, *a1, *a2, *hA, *cA, *lo, *o1, *mo;
    float2 *w1s, *w2s, *w3s;
    cudaGetSymbolAddress((void**)&c1,   g_c1);
    cudaGetSymbolAddress((void**)&c2,   g_c2);
    cudaGetSymbolAddress((void**)&c3,   g_c3);
    cudaGetSymbolAddress((void**)&fc1o, g_fc1);
    cudaGetSymbolAddress((void**)&cnn1, g_cnn1);
    cudaGetSymbolAddress((void**)&cnn2, g_cnn2);
    cudaGetSymbolAddress((void**)&a1,   g_act1);
    cudaGetSymbolAddress((void**)&a2,   g_a);
    cudaGetSymbolAddress((void**)&hA,   g_h);
    cudaGetSymbolAddress((void**)&cA,   g_cst);
    cudaGetSymbolAddress((void**)&lo,   g_lstm_out);
    cudaGetSymbolAddress((void**)&o1,   g_out1);
    cudaGetSymbolAddress((void**)&mo,   g_mo);
    cudaGetSymbolAddress((void**)&w1s,  g_w1s);
    cudaGetSymbolAddress((void**)&w2s,  g_w2s);
    cudaGetSymbolAddress((void**)&w3s,  g_w3s);

    // #1 wsplit conv2 weights (CO=64, NPH=2, KLOC=144, KLOCP=144)
    wsplit_kernel<<<(64 * 288 + 255) / 256, 256>>>(conv2_w, w2s, 64, 2, 144, 144);
    // #2 wsplit conv1 (CO=32, NPH=1, KLOC=75, KLOCP=80)
    wsplit_kernel<<<(32 * 80 + 255) / 256, 256>>>(conv1_w, w1s, 32, 1, 75, 80);
    // #3 conv1 (relu): tiles = 24 x 16 = 384, CIP=3
    conv_mma2<3, 5, 192, 256, 94, 126, 32, 3, true>
        <<<dim3(384, BB), 128>>>(image, w1s, conv1_b, c1);
    // #4 conv2 (relu): tiles = 12 x 8 = 96, CIP=16 (2 phases)  <- ncu capture slot
    conv_mma2<32, 3, 94, 126, 46, 62, 64, 16, true>
        <<<dim3(96, BB), 128>>>(c1, w2s, conv2_b, c2);
    // #5 wsplit conv3 (CO=64, NPH=4, KLOC=144, KLOCP=144)
    wsplit_kernel<<<(64 * 576 + 255) / 256, 256>>>(conv3_w, w3s, 64, 4, 144, 144);
    // #6 conv3 (no relu): tiles = 6 x 4 = 24, CIP=16 (4 phases)
    conv_mma2<64, 3, 46, 62, 22, 30, 64, 16, false>
        <<<dim3(24, BB), 128>>>(c2, w3s, conv3_b, c3);
    // action path
    { dim3 g(BB * TT / 32, 1); lin2_kernel<<<g, 256>>>(act_in, act1_w, act1_b, a1, BB * TT, 16, 2, 0); }
    { dim3 g(BB * TT / 32, 1); lin2_kernel<<<g, 256>>>(a1, act2_w, act2_b, a2, BB * TT, 16, 16, 1); }
    // fc1
    fc1_init_kernel<<<(BB * FC1_N + 255) / 256, 256>>>(fc1_b, fc1o);
    {
        dim3 grid(FC1_N / 64, BB / 64, 33);
        fc1_gemm_kernel<<<grid, 256>>>(c3, fc1_w, fc1o);
    }
    // fc2 / lowd chain
    { dim3 g(BB / 32, 4); lin2_kernel<<<g, 256>>>(fc1o, fc2_w, fc2_b, cnn1, BB, 128, 256, 1); }
    { dim3 g(BB / 32, 4); lin2_kernel<<<g, 256>>>(cnn1, lowd1_w, lowd1_b, cnn2, BB, 128, 128, 0); }
    { dim3 g(BB / 32, 4); lin2_kernel<<<g, 256>>>(cnn2, lowd2_w, lowd2_b, cnn1, BB, 128, 128, 1); }

    // LSTM: 15 waves
    for (int w = 0; w < LL + TT - 1; w++) {
        int l_lo = w - (TT - 1); if (l_lo < 0) l_lo = 0;
        int l_hi = w; if (l_hi > LL - 1) l_hi = LL - 1;
        int ncells = l_hi - l_lo + 1;
        lstm_wave2_kernel<<<ncells * 16, 256>>>(w, a2, cnn1, Wih0, Wih, Whh, bih, bhh, hA, cA, lo);
    }

    // heads
    { dim3 g(BB * TT / 32, 1); lin2_kernel<<<g, 256>>>(lo, out1_w, out1_b, o1, BB * TT, 32, 64, 0); }
    { dim3 g(BB * TT / 32, 1); lin2_kernel<<<g, 256>>>(o1, out2_w, out2_b, mo, BB * TT, 4, 32, 1); }

    finalize_kernel<<<(BB * TT + 255) / 256, 256>>>(mo, gt, out);
}